// round 4
// baseline (speedup 1.0000x reference)
#include <cuda_runtime.h>
#include <cuda_bf16.h>
#include <cstdint>

// Problem constants (fixed by the reference: B=8192, M=64, H=256, P=4096)
#define BATCH   8192
#define HID     256
#define NMOVES  64
#define NPOL    4096
#define KIN     135      // 131 + 4 scalars
#define LDK     136      // padded, %4==0 so rows stay float4-aligned

// ---------------------------------------------------------------------------
// Scratch (no cudaMalloc allowed anywhere)
// ---------------------------------------------------------------------------
__device__ float g_k  [BATCH * LDK];       // concat input, padded
__device__ float g_h1 [BATCH * HID];
__device__ float g_h2 [BATCH * HID];
__device__ float g_h  [BATCH * HID];       // final pre-policy hidden
__device__ float g_WpT[NPOL * HID];        // Wp transposed: [4096][256]

// ---------------------------------------------------------------------------
// Kernel 0: concat [pf | mb | ks | mob | ps] -> g_k (B x 136, col 135 = 0)
// ---------------------------------------------------------------------------
__global__ void concat_kernel(const float* __restrict__ pf,
                              const float* __restrict__ mb,
                              const float* __restrict__ ks,
                              const float* __restrict__ mob,
                              const float* __restrict__ ps)
{
    int idx = blockIdx.x * 256 + threadIdx.x;
    if (idx >= BATCH * LDK) return;
    int r = idx / LDK, j = idx - r * LDK;
    float v;
    if (j < 131)       v = pf[r * 131 + j];
    else if (j == 131) v = mb[r];
    else if (j == 132) v = ks[r];
    else if (j == 133) v = mob[r];
    else if (j == 134) v = ps[r];
    else               v = 0.f;
    g_k[idx] = v;
}

// ---------------------------------------------------------------------------
// Kernel 1: transpose Wp [256][4096] -> g_WpT [4096][256] (for coalesced
// per-column gather dots in the policy epilogue)
// ---------------------------------------------------------------------------
__global__ void transpose_kernel(const float* __restrict__ Wp)
{
    __shared__ float t[32][33];
    int bx = blockIdx.x, by = blockIdx.y;
    int x = bx * 32 + threadIdx.x;               // column of Wp
    #pragma unroll
    for (int i = threadIdx.y; i < 32; i += 8) {
        int y = by * 32 + i;                     // row of Wp
        t[i][threadIdx.x] = Wp[(size_t)y * NPOL + x];
    }
    __syncthreads();
    int xo = by * 32 + threadIdx.x;              // col of WpT (= Wp row)
    #pragma unroll
    for (int i = threadIdx.y; i < 32; i += 8) {
        int yo = bx * 32 + i;                    // row of WpT (= Wp col)
        g_WpT[(size_t)yo * HID + xo] = t[threadIdx.x][i];
    }
}

// ---------------------------------------------------------------------------
// Register-blocked fp32 layer GEMM: C[B,256] = act(A[B,K] @ W[K,256] + b)
// Block: 32 rows, 256 threads. Thread (ty 0..3, tx 0..63) -> 8 rows x 4 cols.
// A loads are warp-broadcast (all lanes of a warp share ty -> same address,
// single L1 sector); W loads are fully coalesced float4 across tx.
// ---------------------------------------------------------------------------
template<int K, int LDA, bool RELU>
__device__ __forceinline__ void layer_body(const float* __restrict__ A,
                                           const float* __restrict__ W,
                                           const float* __restrict__ b,
                                           float* __restrict__ C)
{
    const int tid = threadIdx.x;
    const int ty = tid >> 6, tx = tid & 63;
    const int r0 = blockIdx.x * 32 + ty * 8;
    const int c0 = tx * 4;

    float4 bv = *(const float4*)(b + c0);
    float acc[8][4];
    #pragma unroll
    for (int r = 0; r < 8; r++) {
        acc[r][0] = bv.x; acc[r][1] = bv.y; acc[r][2] = bv.z; acc[r][3] = bv.w;
    }

    constexpr int KF = K & ~3;
    #pragma unroll 2
    for (int k = 0; k < KF; k += 4) {
        float4 w0 = *(const float4*)(W + (size_t)(k + 0) * HID + c0);
        float4 w1 = *(const float4*)(W + (size_t)(k + 1) * HID + c0);
        float4 w2 = *(const float4*)(W + (size_t)(k + 2) * HID + c0);
        float4 w3 = *(const float4*)(W + (size_t)(k + 3) * HID + c0);
        #pragma unroll
        for (int r = 0; r < 8; r++) {
            float4 a = *(const float4*)(A + (size_t)(r0 + r) * LDA + k);
            acc[r][0] = fmaf(a.x, w0.x, fmaf(a.y, w1.x, fmaf(a.z, w2.x, fmaf(a.w, w3.x, acc[r][0]))));
            acc[r][1] = fmaf(a.x, w0.y, fmaf(a.y, w1.y, fmaf(a.z, w2.y, fmaf(a.w, w3.y, acc[r][1]))));
            acc[r][2] = fmaf(a.x, w0.z, fmaf(a.y, w1.z, fmaf(a.z, w2.z, fmaf(a.w, w3.z, acc[r][2]))));
            acc[r][3] = fmaf(a.x, w0.w, fmaf(a.y, w1.w, fmaf(a.z, w2.w, fmaf(a.w, w3.w, acc[r][3]))));
        }
    }
    if constexpr (KF < K) {
        for (int k = KF; k < K; k++) {
            float4 w = *(const float4*)(W + (size_t)k * HID + c0);
            #pragma unroll
            for (int r = 0; r < 8; r++) {
                float a = A[(size_t)(r0 + r) * LDA + k];
                acc[r][0] = fmaf(a, w.x, acc[r][0]);
                acc[r][1] = fmaf(a, w.y, acc[r][1]);
                acc[r][2] = fmaf(a, w.z, acc[r][2]);
                acc[r][3] = fmaf(a, w.w, acc[r][3]);
            }
        }
    }

    #pragma unroll
    for (int r = 0; r < 8; r++) {
        float4 o;
        o.x = RELU ? fmaxf(acc[r][0], 0.f) : acc[r][0];
        o.y = RELU ? fmaxf(acc[r][1], 0.f) : acc[r][1];
        o.z = RELU ? fmaxf(acc[r][2], 0.f) : acc[r][2];
        o.w = RELU ? fmaxf(acc[r][3], 0.f) : acc[r][3];
        *(float4*)(C + (size_t)(r0 + r) * HID + c0) = o;
    }
}

__global__ __launch_bounds__(256, 2) void layer1_kernel(const float* __restrict__ W,
                                                        const float* __restrict__ b)
{ layer_body<KIN, LDK, true>(g_k, W, b, g_h1); }

__global__ __launch_bounds__(256, 2) void layer2_kernel(const float* __restrict__ W,
                                                        const float* __restrict__ b)
{ layer_body<HID, HID, true>(g_h1, W, b, g_h2); }

__global__ __launch_bounds__(256, 2) void layer3_kernel(const float* __restrict__ W,
                                                        const float* __restrict__ b)
{ layer_body<HID, HID, false>(g_h2, W, b, g_h); }

// ---------------------------------------------------------------------------
// Kernel 5: policy head + evals, fused.
//   Phase 1: streamed logsumexp over all 4096 logits per row (never stored).
//   Phase 2: gather 64 move logits via WpT dots, clip, softmax-64, tanh evals.
// Block: 32 rows, 256 threads (ty 0..3 x 8 rows; tx 0..63 x 4-col groups).
// ---------------------------------------------------------------------------
__global__ __launch_bounds__(256, 2) void policy_kernel(
    const float* __restrict__ Wp,   const float* __restrict__ bp,
    const float* __restrict__ We,   const float* __restrict__ be,
    const int*   __restrict__ from_sq, const int* __restrict__ to_sq,
    float* __restrict__ out)
{
    __shared__ float hs[32 * HID];
    __shared__ float WhS[HID];
    __shared__ float WencS[128];
    __shared__ float lse_s[32];
    __shared__ float red_m[8][8];
    __shared__ float red_s[8][8];

    float* out_probs = out;
    float* out_evals = out + (size_t)BATCH * NMOVES;

    const int tid = threadIdx.x;
    const int row0 = blockIdx.x * 32;
    const unsigned FULL = 0xffffffffu;

    // stage h tile + small weights
    {
        const float4* src = (const float4*)(g_h + (size_t)row0 * HID);
        float4* dst = (float4*)hs;
        for (int i = tid; i < 32 * HID / 4; i += 256) dst[i] = src[i];
    }
    WhS[tid] = We[tid];
    if (tid < 128) WencS[tid] = We[HID + tid];
    __syncthreads();

    // ---------------- Phase 1: streamed logsumexp over 4096 columns --------
    const int ty = tid >> 6, tx = tid & 63;
    float m[8], s[8];
    #pragma unroll
    for (int r = 0; r < 8; r++) { m[r] = -1e30f; s[r] = 0.f; }

    for (int tile = 0; tile < NPOL / 256; tile++) {
        const int c = tile * 256 + tx * 4;
        float4 bpv = *(const float4*)(bp + c);
        float acc[8][4];
        #pragma unroll
        for (int r = 0; r < 8; r++) { acc[r][0]=0.f; acc[r][1]=0.f; acc[r][2]=0.f; acc[r][3]=0.f; }

        #pragma unroll 2
        for (int k = 0; k < HID; k += 4) {
            float4 w0 = *(const float4*)(Wp + (size_t)(k + 0) * NPOL + c);
            float4 w1 = *(const float4*)(Wp + (size_t)(k + 1) * NPOL + c);
            float4 w2 = *(const float4*)(Wp + (size_t)(k + 2) * NPOL + c);
            float4 w3 = *(const float4*)(Wp + (size_t)(k + 3) * NPOL + c);
            #pragma unroll
            for (int r = 0; r < 8; r++) {
                float4 a = *(const float4*)(hs + (ty * 8 + r) * HID + k);
                acc[r][0] = fmaf(a.x, w0.x, fmaf(a.y, w1.x, fmaf(a.z, w2.x, fmaf(a.w, w3.x, acc[r][0]))));
                acc[r][1] = fmaf(a.x, w0.y, fmaf(a.y, w1.y, fmaf(a.z, w2.y, fmaf(a.w, w3.y, acc[r][1]))));
                acc[r][2] = fmaf(a.x, w0.z, fmaf(a.y, w1.z, fmaf(a.z, w2.z, fmaf(a.w, w3.z, acc[r][2]))));
                acc[r][3] = fmaf(a.x, w0.w, fmaf(a.y, w1.w, fmaf(a.z, w2.w, fmaf(a.w, w3.w, acc[r][3]))));
            }
        }
        #pragma unroll
        for (int r = 0; r < 8; r++) {
            float x0 = acc[r][0] + bpv.x, x1 = acc[r][1] + bpv.y;
            float x2 = acc[r][2] + bpv.z, x3 = acc[r][3] + bpv.w;
            float xm = fmaxf(fmaxf(x0, x1), fmaxf(x2, x3));
            float mn = fmaxf(m[r], xm);
            s[r] = s[r] * __expf(m[r] - mn)
                 + __expf(x0 - mn) + __expf(x1 - mn)
                 + __expf(x2 - mn) + __expf(x3 - mn);
            m[r] = mn;
        }
    }

    // intra-warp (m,s) merge: all lanes of a warp share the same 8 rows
    #pragma unroll
    for (int off = 16; off; off >>= 1) {
        #pragma unroll
        for (int r = 0; r < 8; r++) {
            float m2 = __shfl_xor_sync(FULL, m[r], off);
            float s2 = __shfl_xor_sync(FULL, s[r], off);
            float mn = fmaxf(m[r], m2);
            s[r] = s[r] * __expf(m[r] - mn) + s2 * __expf(m2 - mn);
            m[r] = mn;
        }
    }
    const int wid = tid >> 5;
    if ((tid & 31) == 0) {
        #pragma unroll
        for (int r = 0; r < 8; r++) { red_m[wid][r] = m[r]; red_s[wid][r] = s[r]; }
    }
    __syncthreads();
    if (tid < 32) {                       // row r: merge warps 2g and 2g+1
        int g = tid >> 3, lr = tid & 7;
        float ma = red_m[2 * g][lr],     sa = red_s[2 * g][lr];
        float mb2 = red_m[2 * g + 1][lr], sb = red_s[2 * g + 1][lr];
        float mn = fmaxf(ma, mb2);
        float ss = sa * __expf(ma - mn) + sb * __expf(mb2 - mn);
        lse_s[tid] = mn + __logf(ss);
    }
    __syncthreads();

    // ---------------- Phase 2: gather / softmax-64 / evals ------------------
    const int lane = tid & 31;
    const int w = tid >> 5;               // warp w handles rows w*4 .. w*4+3
    const float be0 = be[0];

    for (int rr = 0; rr < 4; rr++) {
        const int lrow = w * 4 + rr;
        const int grow = row0 + lrow;
        const float* hrow = hs + lrow * HID;

        // hWh = h . We[:256]   (warp-parallel dot)
        float p = 0.f;
        #pragma unroll
        for (int j = 0; j < 8; j++) p = fmaf(hrow[lane * 8 + j], WhS[lane * 8 + j], p);
        #pragma unroll
        for (int off = 16; off; off >>= 1) p += __shfl_xor_sync(FULL, p, off);
        const float hwh = p;

        float lg[2];
        #pragma unroll
        for (int t = 0; t < 2; t++) {
            const int mI = lane + 32 * t;
            const int f  = from_sq[(size_t)grow * NMOVES + mI];
            const int tt = to_sq  [(size_t)grow * NMOVES + mI];
            const int idx = f * 64 + tt;
            const float4* wc = (const float4*)(g_WpT + (size_t)idx * HID);
            const float4* hv4 = (const float4*)hrow;
            float acc = 0.f;
            #pragma unroll 4
            for (int k4 = 0; k4 < HID / 4; k4++) {
                float4 wv = wc[k4];
                float4 hv = hv4[k4];
                acc = fmaf(wv.x, hv.x, fmaf(wv.y, hv.y, fmaf(wv.z, hv.z, fmaf(wv.w, hv.w, acc))));
            }
            float lgt = acc + bp[idx] - lse_s[lrow];
            lg[t] = fminf(fmaxf(lgt, -10.f), 10.f);

            float ev = tanhf(hwh + WencS[f] + WencS[64 + tt] + be0);
            out_evals[(size_t)grow * NMOVES + mI] = ev;
        }

        // softmax over the 64 clipped log-probs (warp-wide)
        float mx = fmaxf(lg[0], lg[1]);
        #pragma unroll
        for (int off = 16; off; off >>= 1) mx = fmaxf(mx, __shfl_xor_sync(FULL, mx, off));
        float e0 = __expf(lg[0] - mx), e1 = __expf(lg[1] - mx);
        float ssum = e0 + e1;
        #pragma unroll
        for (int off = 16; off; off >>= 1) ssum += __shfl_xor_sync(FULL, ssum, off);
        float inv = 1.0f / ssum;
        out_probs[(size_t)grow * NMOVES + lane]      = e0 * inv;
        out_probs[(size_t)grow * NMOVES + lane + 32] = e1 * inv;
    }
}

// ---------------------------------------------------------------------------
// kernel_launch — graph-capturable: kernel launches only, no allocs/syncs.
// ---------------------------------------------------------------------------
extern "C" void kernel_launch(void* const* d_in, const int* in_sizes, int n_in,
                              void* d_out, int out_size)
{
    const float* pf   = (const float*)d_in[0];
    const float* mb   = (const float*)d_in[1];
    const float* ks   = (const float*)d_in[2];
    const float* mob  = (const float*)d_in[3];
    const float* ps   = (const float*)d_in[4];
    const int*   fsq  = (const int*)  d_in[5];
    const int*   tsq  = (const int*)  d_in[6];
    const float* W1   = (const float*)d_in[7];
    const float* b1   = (const float*)d_in[8];
    const float* W2   = (const float*)d_in[9];
    const float* b2   = (const float*)d_in[10];
    const float* W3   = (const float*)d_in[11];
    const float* b3   = (const float*)d_in[12];
    const float* We   = (const float*)d_in[13];
    const float* be   = (const float*)d_in[14];
    const float* Wp   = (const float*)d_in[15];
    const float* bp   = (const float*)d_in[16];
    float* out = (float*)d_out;

    concat_kernel<<<(BATCH * LDK + 255) / 256, 256>>>(pf, mb, ks, mob, ps);
    transpose_kernel<<<dim3(NPOL / 32, HID / 32), dim3(32, 8)>>>(Wp);
    layer1_kernel<<<BATCH / 32, 256>>>(W1, b1);
    layer2_kernel<<<BATCH / 32, 256>>>(W2, b2);
    layer3_kernel<<<BATCH / 32, 256>>>(W3, b3);
    policy_kernel<<<BATCH / 32, 256>>>(Wp, bp, We, be, fsq, tsq, out);
}

// round 6
// speedup vs baseline: 1.4645x; 1.4645x over previous
#include <cuda_runtime.h>
#include <cuda_bf16.h>
#include <cstdint>

// Problem constants (fixed by the reference: B=8192, M=64, H=256, P=4096)
#define BATCH   8192
#define HID     256
#define NMOVES  64
#define NPOL    4096
#define KIN     135
#define LDK     136

// ===========================================================================
// Scratch (no cudaMalloc allowed anywhere)
// ===========================================================================
__device__ float g_k   [BATCH * LDK];
__device__ float g_h1  [BATCH * HID];
__device__ float g_h2  [BATCH * HID];
__device__ float g_h   [BATCH * HID];       // final hidden, fp32 (gather kernel)
__device__ float g_WpT [NPOL * HID];        // Wp^T fp32 (gather kernel)
__device__ uint2 g_hB  [BATCH * (HID/2)];   // h  bf16 hi/lo interleaved per k-pair
__device__ uint2 g_WpB [NPOL  * (HID/2)];   // WpT bf16 hi/lo interleaved per k-pair
__device__ float g_lse [BATCH];

// ===========================================================================
// Helpers
// ===========================================================================
__device__ __forceinline__ unsigned short bf16_bits(__nv_bfloat16 h) {
    return *reinterpret_cast<unsigned short*>(&h);
}

// pack (a,b) -> {hi(a)|hi(b)<<16 , lo(a)|lo(b)<<16}   (lo = residual in bf16)
__device__ __forceinline__ uint2 pack_hilo2(float a, float b) {
    __nv_bfloat16 ha = __float2bfloat16(a);
    __nv_bfloat16 hb = __float2bfloat16(b);
    __nv_bfloat16 la = __float2bfloat16(a - __bfloat162float(ha));
    __nv_bfloat16 lb = __float2bfloat16(b - __bfloat162float(hb));
    uint2 u;
    u.x = (uint32_t)bf16_bits(ha) | ((uint32_t)bf16_bits(hb) << 16);
    u.y = (uint32_t)bf16_bits(la) | ((uint32_t)bf16_bits(lb) << 16);
    return u;
}

// m16n8k16 bf16 MMA with fp32 accumulate (sm_80+ instruction; fallback HMMA
// on Blackwell — compiles for plain compute_100, unlike tcgen05).
__device__ __forceinline__ void mma16816(float d[4],
                                         uint32_t a0, uint32_t a1,
                                         uint32_t a2, uint32_t a3,
                                         uint32_t b0, uint32_t b1) {
    asm volatile(
        "mma.sync.aligned.m16n8k16.row.col.f32.bf16.bf16.f32 "
        "{%0,%1,%2,%3}, {%4,%5,%6,%7}, {%8,%9}, {%0,%1,%2,%3};"
        : "+f"(d[0]), "+f"(d[1]), "+f"(d[2]), "+f"(d[3])
        : "r"(a0), "r"(a1), "r"(a2), "r"(a3), "r"(b0), "r"(b1));
}

// ===========================================================================
// Kernel 0: concat
// ===========================================================================
__global__ void concat_kernel(const float* __restrict__ pf,
                              const float* __restrict__ mb,
                              const float* __restrict__ ks,
                              const float* __restrict__ mob,
                              const float* __restrict__ ps)
{
    int idx = blockIdx.x * 256 + threadIdx.x;
    if (idx >= BATCH * LDK) return;
    int r = idx / LDK, j = idx - r * LDK;
    float v;
    if (j < 131)       v = pf[r * 131 + j];
    else if (j == 131) v = mb[r];
    else if (j == 132) v = ks[r];
    else if (j == 133) v = mob[r];
    else if (j == 134) v = ps[r];
    else               v = 0.f;
    g_k[idx] = v;
}

// ===========================================================================
// Kernel 1: transpose Wp [256][4096] -> g_WpT [4096][256] (fp32)
// ===========================================================================
__global__ void transpose_kernel(const float* __restrict__ Wp)
{
    __shared__ float t[32][33];
    int bx = blockIdx.x, by = blockIdx.y;
    int x = bx * 32 + threadIdx.x;
    #pragma unroll
    for (int i = threadIdx.y; i < 32; i += 8) {
        int y = by * 32 + i;
        t[i][threadIdx.x] = Wp[(size_t)y * NPOL + x];
    }
    __syncthreads();
    int xo = by * 32 + threadIdx.x;
    #pragma unroll
    for (int i = threadIdx.y; i < 32; i += 8) {
        int yo = bx * 32 + i;
        g_WpT[(size_t)yo * HID + xo] = t[threadIdx.x][i];
    }
}

// ===========================================================================
// Kernel 2: pack WpT into bf16 hi/lo interleaved k-pairs for the MMA kernel
// ===========================================================================
__global__ void pack_wp_kernel()
{
    int idx = blockIdx.x * 256 + threadIdx.x;
    if (idx >= NPOL * (HID / 2)) return;
    int n = idx >> 7, kp = idx & 127;
    float v0 = g_WpT[(size_t)n * HID + 2 * kp];
    float v1 = g_WpT[(size_t)n * HID + 2 * kp + 1];
    g_WpB[idx] = pack_hilo2(v0, v1);
}

// ===========================================================================
// Register-blocked fp32 layer GEMM (known-correct R4 code)
// ===========================================================================
template<int K, int LDA, bool RELU, bool SPLIT>
__device__ __forceinline__ void layer_body(const float* __restrict__ A,
                                           const float* __restrict__ W,
                                           const float* __restrict__ b,
                                           float* __restrict__ C)
{
    const int tid = threadIdx.x;
    const int ty = tid >> 6, tx = tid & 63;
    const int r0 = blockIdx.x * 32 + ty * 8;
    const int c0 = tx * 4;

    float4 bv = *(const float4*)(b + c0);
    float acc[8][4];
    #pragma unroll
    for (int r = 0; r < 8; r++) {
        acc[r][0] = bv.x; acc[r][1] = bv.y; acc[r][2] = bv.z; acc[r][3] = bv.w;
    }

    constexpr int KF = K & ~3;
    #pragma unroll 2
    for (int k = 0; k < KF; k += 4) {
        float4 w0 = *(const float4*)(W + (size_t)(k + 0) * HID + c0);
        float4 w1 = *(const float4*)(W + (size_t)(k + 1) * HID + c0);
        float4 w2 = *(const float4*)(W + (size_t)(k + 2) * HID + c0);
        float4 w3 = *(const float4*)(W + (size_t)(k + 3) * HID + c0);
        #pragma unroll
        for (int r = 0; r < 8; r++) {
            float4 a = *(const float4*)(A + (size_t)(r0 + r) * LDA + k);
            acc[r][0] = fmaf(a.x, w0.x, fmaf(a.y, w1.x, fmaf(a.z, w2.x, fmaf(a.w, w3.x, acc[r][0]))));
            acc[r][1] = fmaf(a.x, w0.y, fmaf(a.y, w1.y, fmaf(a.z, w2.y, fmaf(a.w, w3.y, acc[r][1]))));
            acc[r][2] = fmaf(a.x, w0.z, fmaf(a.y, w1.z, fmaf(a.z, w2.z, fmaf(a.w, w3.z, acc[r][2]))));
            acc[r][3] = fmaf(a.x, w0.w, fmaf(a.y, w1.w, fmaf(a.z, w2.w, fmaf(a.w, w3.w, acc[r][3]))));
        }
    }
    if constexpr (KF < K) {
        for (int k = KF; k < K; k++) {
            float4 w = *(const float4*)(W + (size_t)k * HID + c0);
            #pragma unroll
            for (int r = 0; r < 8; r++) {
                float a = A[(size_t)(r0 + r) * LDA + k];
                acc[r][0] = fmaf(a, w.x, acc[r][0]);
                acc[r][1] = fmaf(a, w.y, acc[r][1]);
                acc[r][2] = fmaf(a, w.z, acc[r][2]);
                acc[r][3] = fmaf(a, w.w, acc[r][3]);
            }
        }
    }

    #pragma unroll
    for (int r = 0; r < 8; r++) {
        float4 o;
        o.x = RELU ? fmaxf(acc[r][0], 0.f) : acc[r][0];
        o.y = RELU ? fmaxf(acc[r][1], 0.f) : acc[r][1];
        o.z = RELU ? fmaxf(acc[r][2], 0.f) : acc[r][2];
        o.w = RELU ? fmaxf(acc[r][3], 0.f) : acc[r][3];
        size_t oidx = (size_t)(r0 + r) * HID + c0;
        *(float4*)(C + oidx) = o;
        if constexpr (SPLIT) {
            size_t pidx = (size_t)(r0 + r) * (HID / 2) + (c0 >> 1);
            g_hB[pidx]     = pack_hilo2(o.x, o.y);
            g_hB[pidx + 1] = pack_hilo2(o.z, o.w);
        }
    }
}

__global__ __launch_bounds__(256, 2) void layer1_kernel(const float* __restrict__ W,
                                                        const float* __restrict__ b)
{ layer_body<KIN, LDK, true, false>(g_k, W, b, g_h1); }

__global__ __launch_bounds__(256, 2) void layer2_kernel(const float* __restrict__ W,
                                                        const float* __restrict__ b)
{ layer_body<HID, HID, true, false>(g_h1, W, b, g_h2); }

__global__ __launch_bounds__(256, 2) void layer3_kernel(const float* __restrict__ W,
                                                        const float* __restrict__ b)
{ layer_body<HID, HID, false, true>(g_h2, W, b, g_h); }

// ===========================================================================
// Kernel 5: HMMA policy logsumexp.
//   Per CTA: 64 rows. logits[64,4096] = h @ Wp via mma.sync m16n8k16 bf16
//   (hi/lo split, 3 MMAs per fragment pair), fp32 accumulate. N is swept in
//   16 slabs of 256 columns (8 warps x 32 cols); the online (m,s) logsumexp
//   epilogue runs per slab so logits are never stored. Writes g_lse[row].
//
// SMEM layout (dynamic):
//   As  @ 0     : 64 rows x 132 uint2 (1056 B/row, +32B pad -> conflict-free
//                 fragment loads)                                   = 67584 B
//   bps @ 67584 : 4096 floats (bias)                                = 16384 B
//   red @ 83968 : m[64][8], s[64][8]                                =  4096 B
// ===========================================================================
#define POL_SMEM 88064
#define AROW 132   // uint2 per padded A row

__global__ __launch_bounds__(256, 1)
void policy_lse_kernel(const float* __restrict__ bp)
{
    extern __shared__ char dsm[];
    uint2* As    = (uint2*)dsm;                    // [64][AROW]
    float* bps   = (float*)(dsm + 67584);          // [4096]
    float* red_m = (float*)(dsm + 83968);          // [64][8]
    float* red_s = (float*)(dsm + 83968 + 2048);   // [64][8]

    const int tid  = threadIdx.x;
    const int wid  = tid >> 5;
    const int lane = tid & 31;
    const int gid  = lane >> 2;       // 0..7
    const int tig  = lane & 3;        // 0..3
    const int row0 = blockIdx.x * 64;
    const unsigned FULL = 0xffffffffu;

    // stage A (64 x 128 uint2) and bias
    for (int i = tid; i < 64 * 128; i += 256) {
        int r = i >> 7, c = i & 127;
        As[r * AROW + c] = g_hB[(size_t)(row0 + r) * 128 + c];
    }
    for (int i = tid; i < NPOL; i += 256) bps[i] = bp[i];
    __syncthreads();

    // per-lane row pointers for the 8 fragment rows (4 m-tiles x 2 halves)
    const uint2* Ar[4][2];
    #pragma unroll
    for (int mt = 0; mt < 4; mt++) {
        Ar[mt][0] = As + (gid + 16 * mt) * AROW;
        Ar[mt][1] = As + (gid + 8 + 16 * mt) * AROW;
    }
    const float2* bps2 = (const float2*)bps;

    float m[8], s[8];
    #pragma unroll
    for (int j = 0; j < 8; j++) { m[j] = -1e30f; s[j] = 0.f; }

    for (int it = 0; it < 16; it++) {
        const int nbase = it * 256 + wid * 32;
        const uint2* Bp[4];
        #pragma unroll
        for (int nt = 0; nt < 4; nt++)
            Bp[nt] = g_WpB + (size_t)(nbase + nt * 8 + gid) * 128;

        float acc[4][4][4];
        #pragma unroll
        for (int mt = 0; mt < 4; mt++)
            #pragma unroll
            for (int nt = 0; nt < 4; nt++)
                #pragma unroll
                for (int q = 0; q < 4; q++) acc[mt][nt][q] = 0.f;

        #pragma unroll 1
        for (int ks = 0; ks < 16; ks++) {
            const int kb = ks * 8 + tig;
            uint2 a[4][4];
            #pragma unroll
            for (int mt = 0; mt < 4; mt++) {
                a[mt][0] = Ar[mt][0][kb];
                a[mt][1] = Ar[mt][1][kb];
                a[mt][2] = Ar[mt][0][kb + 4];
                a[mt][3] = Ar[mt][1][kb + 4];
            }
            uint2 b[4][2];
            #pragma unroll
            for (int nt = 0; nt < 4; nt++) {
                b[nt][0] = __ldg(Bp[nt] + kb);
                b[nt][1] = __ldg(Bp[nt] + kb + 4);
            }
            #pragma unroll
            for (int mt = 0; mt < 4; mt++) {
                #pragma unroll
                for (int nt = 0; nt < 4; nt++) {
                    // hi*hi
                    mma16816(acc[mt][nt],
                             a[mt][0].x, a[mt][1].x, a[mt][2].x, a[mt][3].x,
                             b[nt][0].x, b[nt][1].x);
                    // hi*lo
                    mma16816(acc[mt][nt],
                             a[mt][0].x, a[mt][1].x, a[mt][2].x, a[mt][3].x,
                             b[nt][0].y, b[nt][1].y);
                    // lo*hi
                    mma16816(acc[mt][nt],
                             a[mt][0].y, a[mt][1].y, a[mt][2].y, a[mt][3].y,
                             b[nt][0].x, b[nt][1].x);
                }
            }
        }

        // online logsumexp over this 32-column slab
        #pragma unroll
        for (int mt = 0; mt < 4; mt++) {
            #pragma unroll
            for (int h = 0; h < 2; h++) {
                const int j = mt * 2 + h;
                float v[8];
                #pragma unroll
                for (int nt = 0; nt < 4; nt++) {
                    float2 bb = bps2[it * 128 + wid * 16 + nt * 4 + tig];
                    v[nt * 2]     = acc[mt][nt][2 * h]     + bb.x;
                    v[nt * 2 + 1] = acc[mt][nt][2 * h + 1] + bb.y;
                }
                float vmax = v[0];
                #pragma unroll
                for (int q = 1; q < 8; q++) vmax = fmaxf(vmax, v[q]);
                float mn = fmaxf(m[j], vmax);
                float as = 0.f;
                #pragma unroll
                for (int q = 0; q < 8; q++) as += __expf(v[q] - mn);
                s[j] = s[j] * __expf(m[j] - mn) + as;
                m[j] = mn;
            }
        }
    }

    // cross-tig merge (lanes sharing a row differ only in tig bits)
    #pragma unroll
    for (int j = 0; j < 8; j++) {
        #pragma unroll
        for (int off = 1; off <= 2; off <<= 1) {
            float m2 = __shfl_xor_sync(FULL, m[j], off);
            float s2 = __shfl_xor_sync(FULL, s[j], off);
            float mn = fmaxf(m[j], m2);
            s[j] = s[j] * __expf(m[j] - mn) + s2 * __expf(m2 - mn);
            m[j] = mn;
        }
        if (tig == 0) {
            red_m[(gid + 8 * j) * 8 + wid] = m[j];
            red_s[(gid + 8 * j) * 8 + wid] = s[j];
        }
    }
    __syncthreads();

    // cross-warp merge + write lse
    if (tid < 64) {
        float mm = -1e30f, ss = 0.f;
        #pragma unroll
        for (int w = 0; w < 8; w++) {
            float mw = red_m[tid * 8 + w], sw = red_s[tid * 8 + w];
            float mn = fmaxf(mm, mw);
            ss = ss * __expf(mm - mn) + sw * __expf(mw - mn);
            mm = mn;
        }
        g_lse[row0 + tid] = mm + __logf(ss);
    }
}

// ===========================================================================
// Kernel 6: gather 64 move logits (fp32 WpT dots), softmax-64, tanh evals.
// ===========================================================================
__global__ __launch_bounds__(256, 2) void gather_kernel(
    const float* __restrict__ bp,
    const float* __restrict__ We, const float* __restrict__ be,
    const int* __restrict__ from_sq, const int* __restrict__ to_sq,
    float* __restrict__ out)
{
    __shared__ float hs[32 * HID];
    __shared__ float WhS[HID];
    __shared__ float WencS[128];

    float* out_probs = out;
    float* out_evals = out + (size_t)BATCH * NMOVES;

    const int tid = threadIdx.x;
    const int row0 = blockIdx.x * 32;
    const unsigned FULL = 0xffffffffu;

    {
        const float4* src = (const float4*)(g_h + (size_t)row0 * HID);
        float4* dst = (float4*)hs;
        for (int i = tid; i < 32 * HID / 4; i += 256) dst[i] = src[i];
    }
    WhS[tid] = We[tid];
    if (tid < 128) WencS[tid] = We[HID + tid];
    __syncthreads();

    const int lane = tid & 31;
    const int w = tid >> 5;
    const float be0 = be[0];

    for (int rr = 0; rr < 4; rr++) {
        const int lrow = w * 4 + rr;
        const int grow = row0 + lrow;
        const float* hrow = hs + lrow * HID;
        const float lse = g_lse[grow];

        float p = 0.f;
        #pragma unroll
        for (int j = 0; j < 8; j++) p = fmaf(hrow[lane * 8 + j], WhS[lane * 8 + j], p);
        #pragma unroll
        for (int off = 16; off; off >>= 1) p += __shfl_xor_sync(FULL, p, off);
        const float hwh = p;

        float lg[2];
        #pragma unroll
        for (int t = 0; t < 2; t++) {
            const int mI = lane + 32 * t;
            const int f  = from_sq[(size_t)grow * NMOVES + mI];
            const int tt = to_sq  [(size_t)grow * NMOVES + mI];
            const int idx = f * 64 + tt;
            const float4* wc  = (const float4*)(g_WpT + (size_t)idx * HID);
            const float4* hv4 = (const float4*)hrow;
            float acc = 0.f;
            #pragma unroll 4
            for (int k4 = 0; k4 < HID / 4; k4++) {
                float4 wv = wc[k4];
                float4 hv = hv4[k4];
                acc = fmaf(wv.x, hv.x, fmaf(wv.y, hv.y, fmaf(wv.z, hv.z, fmaf(wv.w, hv.w, acc))));
            }
            float lgt = acc + bp[idx] - lse;
            lg[t] = fminf(fmaxf(lgt, -10.f), 10.f);

            out_evals[(size_t)grow * NMOVES + mI] =
                tanhf(hwh + WencS[f] + WencS[64 + tt] + be0);
        }

        float mx = fmaxf(lg[0], lg[1]);
        #pragma unroll
        for (int off = 16; off; off >>= 1) mx = fmaxf(mx, __shfl_xor_sync(FULL, mx, off));
        float e0 = __expf(lg[0] - mx), e1 = __expf(lg[1] - mx);
        float ssum = e0 + e1;
        #pragma unroll
        for (int off = 16; off; off >>= 1) ssum += __shfl_xor_sync(FULL, ssum, off);
        float inv = 1.0f / ssum;
        out_probs[(size_t)grow * NMOVES + lane]      = e0 * inv;
        out_probs[(size_t)grow * NMOVES + lane + 32] = e1 * inv;
    }
}

// ===========================================================================
// kernel_launch — graph-capturable: kernel launches only, no allocs/syncs.
// ===========================================================================
extern "C" void kernel_launch(void* const* d_in, const int* in_sizes, int n_in,
                              void* d_out, int out_size)
{
    const float* pf   = (const float*)d_in[0];
    const float* mb   = (const float*)d_in[1];
    const float* ks   = (const float*)d_in[2];
    const float* mob  = (const float*)d_in[3];
    const float* ps   = (const float*)d_in[4];
    const int*   fsq  = (const int*)  d_in[5];
    const int*   tsq  = (const int*)  d_in[6];
    const float* W1   = (const float*)d_in[7];
    const float* b1   = (const float*)d_in[8];
    const float* W2   = (const float*)d_in[9];
    const float* b2   = (const float*)d_in[10];
    const float* W3   = (const float*)d_in[11];
    const float* b3   = (const float*)d_in[12];
    const float* We   = (const float*)d_in[13];
    const float* be   = (const float*)d_in[14];
    const float* Wp   = (const float*)d_in[15];
    const float* bp   = (const float*)d_in[16];
    float* out = (float*)d_out;

    static bool attr_set = false;
    if (!attr_set) {
        cudaFuncSetAttribute(policy_lse_kernel,
                             cudaFuncAttributeMaxDynamicSharedMemorySize,
                             POL_SMEM);
        attr_set = true;
    }

    concat_kernel<<<(BATCH * LDK + 255) / 256, 256>>>(pf, mb, ks, mob, ps);
    transpose_kernel<<<dim3(NPOL / 32, HID / 32), dim3(32, 8)>>>(Wp);
    pack_wp_kernel<<<(NPOL * (HID / 2) + 255) / 256, 256>>>();
    layer1_kernel<<<BATCH / 32, 256>>>(W1, b1);
    layer2_kernel<<<BATCH / 32, 256>>>(W2, b2);
    layer3_kernel<<<BATCH / 32, 256>>>(W3, b3);
    policy_lse_kernel<<<BATCH / 64, 256, POL_SMEM>>>(bp);
    gather_kernel<<<BATCH / 32, 256>>>(bp, We, be, fsq, tsq, out);
}

// round 10
// speedup vs baseline: 1.4858x; 1.0145x over previous
#include <cuda_runtime.h>
#include <cuda_bf16.h>
#include <cstdint>

// Problem constants (fixed by the reference: B=8192, M=64, H=256, P=4096)
#define BATCH   8192
#define HID     256
#define NMOVES  64
#define NPOL    4096
#define KIN     135
#define LDK     136
#define KPH     128       // K pairs for K=256

// ===========================================================================
// Scratch (no cudaMalloc allowed anywhere) — identical set/sizes to the
// R6 passing build.
// ===========================================================================
__device__ float g_k   [BATCH * LDK];
__device__ float g_h1  [BATCH * HID];
__device__ float g_h2  [BATCH * HID];
__device__ float g_h   [BATCH * HID];       // final hidden, fp32 (gather kernel)
__device__ float g_WpT [NPOL * HID];        // Wp^T fp32 (gather kernel)
__device__ uint2 g_hB  [BATCH * KPH];       // h  bf16 hi/lo interleaved per k-pair
__device__ uint2 g_WpB [NPOL  * KPH];       // WpT bf16 hi/lo interleaved per k-pair
__device__ float g_lse [BATCH];

// ===========================================================================
// Helpers
// ===========================================================================
__device__ __forceinline__ unsigned short bf16_bits(__nv_bfloat16 h) {
    return *reinterpret_cast<unsigned short*>(&h);
}

// pack (a,b) -> {hi(a)|hi(b)<<16 , lo(a)|lo(b)<<16}   (lo = residual in bf16)
__device__ __forceinline__ uint2 pack_hilo2(float a, float b) {
    __nv_bfloat16 ha = __float2bfloat16(a);
    __nv_bfloat16 hb = __float2bfloat16(b);
    __nv_bfloat16 la = __float2bfloat16(a - __bfloat162float(ha));
    __nv_bfloat16 lb = __float2bfloat16(b - __bfloat162float(hb));
    uint2 u;
    u.x = (uint32_t)bf16_bits(ha) | ((uint32_t)bf16_bits(hb) << 16);
    u.y = (uint32_t)bf16_bits(la) | ((uint32_t)bf16_bits(lb) << 16);
    return u;
}

// m16n8k16 bf16 MMA, fp32 accumulate (sm_80+; fallback HMMA on Blackwell)
__device__ __forceinline__ void mma16816(float d[4],
                                         uint32_t a0, uint32_t a1,
                                         uint32_t a2, uint32_t a3,
                                         uint32_t b0, uint32_t b1) {
    asm volatile(
        "mma.sync.aligned.m16n8k16.row.col.f32.bf16.bf16.f32 "
        "{%0,%1,%2,%3}, {%4,%5,%6,%7}, {%8,%9}, {%0,%1,%2,%3};"
        : "+f"(d[0]), "+f"(d[1]), "+f"(d[2]), "+f"(d[3])
        : "r"(a0), "r"(a1), "r"(a2), "r"(a3), "r"(b0), "r"(b1));
}

// ===========================================================================
// Kernel 0: concat [pf | mb | ks | mob | ps] -> g_k (B x 136, col 135 = 0)
// (byte-identical to the R6 passing build)
// ===========================================================================
__global__ void concat_kernel(const float* __restrict__ pf,
                              const float* __restrict__ mb,
                              const float* __restrict__ ks,
                              const float* __restrict__ mob,
                              const float* __restrict__ ps)
{
    int idx = blockIdx.x * 256 + threadIdx.x;
    if (idx >= BATCH * LDK) return;
    int r = idx / LDK, j = idx - r * LDK;
    float v;
    if (j < 131)       v = pf[r * 131 + j];
    else if (j == 131) v = mb[r];
    else if (j == 132) v = ks[r];
    else if (j == 133) v = mob[r];
    else if (j == 134) v = ps[r];
    else               v = 0.f;
    g_k[idx] = v;
}

// ===========================================================================
// Kernel 1: fused transpose+pack. Writes g_WpT [4096][256] (fp32, gather)
// AND g_WpB [4096][128] (bf16 hi/lo pairs, policy B) from one smem tile.
// Fusing saves a 4MB WpT re-read and makes policy the 6th launch (ncu -s 5).
// ===========================================================================
__global__ void transpose_pack_kernel(const float* __restrict__ Wp)
{
    __shared__ float t[32][33];
    int bx = blockIdx.x, by = blockIdx.y;
    int x = bx * 32 + threadIdx.x;               // n-column of Wp
    #pragma unroll
    for (int i = threadIdx.y; i < 32; i += 8) {
        int y = by * 32 + i;                     // k-row of Wp
        t[i][threadIdx.x] = Wp[(size_t)y * NPOL + x];
    }
    __syncthreads();
    // fp32 transpose out (as in R6)
    int xo = by * 32 + threadIdx.x;              // k
    #pragma unroll
    for (int i = threadIdx.y; i < 32; i += 8) {
        int yo = bx * 32 + i;                    // n
        g_WpT[(size_t)yo * HID + xo] = t[threadIdx.x][i];
    }
    // packed bf16 hi/lo out: g_WpB[n*128 + kp] = pack(Wp[2kp][n], Wp[2kp+1][n])
    if (threadIdx.x < 16) {
        #pragma unroll
        for (int i = threadIdx.y; i < 32; i += 8) {
            int n = bx * 32 + i;
            g_WpB[(size_t)n * KPH + by * 16 + threadIdx.x] =
                pack_hilo2(t[2 * threadIdx.x][i], t[2 * threadIdx.x + 1][i]);
        }
    }
}

// ===========================================================================
// Register-blocked fp32 layer GEMM (byte-identical to the R6 passing build)
// ===========================================================================
template<int K, int LDA, bool RELU, bool SPLIT>
__device__ __forceinline__ void layer_body(const float* __restrict__ A,
                                           const float* __restrict__ W,
                                           const float* __restrict__ b,
                                           float* __restrict__ C)
{
    const int tid = threadIdx.x;
    const int ty = tid >> 6, tx = tid & 63;
    const int r0 = blockIdx.x * 32 + ty * 8;
    const int c0 = tx * 4;

    float4 bv = *(const float4*)(b + c0);
    float acc[8][4];
    #pragma unroll
    for (int r = 0; r < 8; r++) {
        acc[r][0] = bv.x; acc[r][1] = bv.y; acc[r][2] = bv.z; acc[r][3] = bv.w;
    }

    constexpr int KF = K & ~3;
    #pragma unroll 2
    for (int k = 0; k < KF; k += 4) {
        float4 w0 = *(const float4*)(W + (size_t)(k + 0) * HID + c0);
        float4 w1 = *(const float4*)(W + (size_t)(k + 1) * HID + c0);
        float4 w2 = *(const float4*)(W + (size_t)(k + 2) * HID + c0);
        float4 w3 = *(const float4*)(W + (size_t)(k + 3) * HID + c0);
        #pragma unroll
        for (int r = 0; r < 8; r++) {
            float4 a = *(const float4*)(A + (size_t)(r0 + r) * LDA + k);
            acc[r][0] = fmaf(a.x, w0.x, fmaf(a.y, w1.x, fmaf(a.z, w2.x, fmaf(a.w, w3.x, acc[r][0]))));
            acc[r][1] = fmaf(a.x, w0.y, fmaf(a.y, w1.y, fmaf(a.z, w2.y, fmaf(a.w, w3.y, acc[r][1]))));
            acc[r][2] = fmaf(a.x, w0.z, fmaf(a.y, w1.z, fmaf(a.z, w2.z, fmaf(a.w, w3.z, acc[r][2]))));
            acc[r][3] = fmaf(a.x, w0.w, fmaf(a.y, w1.w, fmaf(a.z, w2.w, fmaf(a.w, w3.w, acc[r][3]))));
        }
    }
    if constexpr (KF < K) {
        for (int k = KF; k < K; k++) {
            float4 w = *(const float4*)(W + (size_t)k * HID + c0);
            #pragma unroll
            for (int r = 0; r < 8; r++) {
                float a = A[(size_t)(r0 + r) * LDA + k];
                acc[r][0] = fmaf(a, w.x, acc[r][0]);
                acc[r][1] = fmaf(a, w.y, acc[r][1]);
                acc[r][2] = fmaf(a, w.z, acc[r][2]);
                acc[r][3] = fmaf(a, w.w, acc[r][3]);
            }
        }
    }

    #pragma unroll
    for (int r = 0; r < 8; r++) {
        float4 o;
        o.x = RELU ? fmaxf(acc[r][0], 0.f) : acc[r][0];
        o.y = RELU ? fmaxf(acc[r][1], 0.f) : acc[r][1];
        o.z = RELU ? fmaxf(acc[r][2], 0.f) : acc[r][2];
        o.w = RELU ? fmaxf(acc[r][3], 0.f) : acc[r][3];
        size_t oidx = (size_t)(r0 + r) * HID + c0;
        *(float4*)(C + oidx) = o;
        if constexpr (SPLIT) {
            size_t pidx = (size_t)(r0 + r) * KPH + (c0 >> 1);
            g_hB[pidx]     = pack_hilo2(o.x, o.y);
            g_hB[pidx + 1] = pack_hilo2(o.z, o.w);
        }
    }
}

__global__ __launch_bounds__(256, 2) void layer1_kernel(const float* __restrict__ W,
                                                        const float* __restrict__ b)
{ layer_body<KIN, LDK, true, false>(g_k, W, b, g_h1); }

__global__ __launch_bounds__(256, 2) void layer2_kernel(const float* __restrict__ W,
                                                        const float* __restrict__ b)
{ layer_body<HID, HID, true, false>(g_h1, W, b, g_h2); }

__global__ __launch_bounds__(256, 2) void layer3_kernel(const float* __restrict__ W,
                                                        const float* __restrict__ b)
{ layer_body<HID, HID, false, true>(g_h2, W, b, g_h); }

// ===========================================================================
// Kernel 5: HMMA policy logsumexp — byte-identical to the R6 passing build.
// ===========================================================================
#define POL_SMEM 88064
#define AROW 132   // uint2 per padded A row

__global__ __launch_bounds__(256, 1)
void policy_lse_kernel(const float* __restrict__ bp)
{
    extern __shared__ char dsm[];
    uint2* As    = (uint2*)dsm;                    // [64][AROW]
    float* bps   = (float*)(dsm + 67584);          // [4096]
    float* red_m = (float*)(dsm + 83968);          // [64][8]
    float* red_s = (float*)(dsm + 83968 + 2048);   // [64][8]

    const int tid  = threadIdx.x;
    const int wid  = tid >> 5;
    const int lane = tid & 31;
    const int gid  = lane >> 2;
    const int tig  = lane & 3;
    const int row0 = blockIdx.x * 64;
    const unsigned FULL = 0xffffffffu;

    for (int i = tid; i < 64 * 128; i += 256) {
        int r = i >> 7, c = i & 127;
        As[r * AROW + c] = g_hB[(size_t)(row0 + r) * 128 + c];
    }
    for (int i = tid; i < NPOL; i += 256) bps[i] = bp[i];
    __syncthreads();

    const uint2* Ar[4][2];
    #pragma unroll
    for (int mt = 0; mt < 4; mt++) {
        Ar[mt][0] = As + (gid + 16 * mt) * AROW;
        Ar[mt][1] = As + (gid + 8 + 16 * mt) * AROW;
    }
    const float2* bps2 = (const float2*)bps;

    float m[8], s[8];
    #pragma unroll
    for (int j = 0; j < 8; j++) { m[j] = -1e30f; s[j] = 0.f; }

    for (int it = 0; it < 16; it++) {
        const int nbase = it * 256 + wid * 32;
        const uint2* Bp[4];
        #pragma unroll
        for (int nt = 0; nt < 4; nt++)
            Bp[nt] = g_WpB + (size_t)(nbase + nt * 8 + gid) * 128;

        float acc[4][4][4];
        #pragma unroll
        for (int mt = 0; mt < 4; mt++)
            #pragma unroll
            for (int nt = 0; nt < 4; nt++)
                #pragma unroll
                for (int q = 0; q < 4; q++) acc[mt][nt][q] = 0.f;

        #pragma unroll 1
        for (int ksi = 0; ksi < 16; ksi++) {
            const int kb = ksi * 8 + tig;
            uint2 a[4][4];
            #pragma unroll
            for (int mt = 0; mt < 4; mt++) {
                a[mt][0] = Ar[mt][0][kb];
                a[mt][1] = Ar[mt][1][kb];
                a[mt][2] = Ar[mt][0][kb + 4];
                a[mt][3] = Ar[mt][1][kb + 4];
            }
            uint2 b[4][2];
            #pragma unroll
            for (int nt = 0; nt < 4; nt++) {
                b[nt][0] = __ldg(Bp[nt] + kb);
                b[nt][1] = __ldg(Bp[nt] + kb + 4);
            }
            #pragma unroll
            for (int mt = 0; mt < 4; mt++) {
                #pragma unroll
                for (int nt = 0; nt < 4; nt++) {
                    mma16816(acc[mt][nt],
                             a[mt][0].x, a[mt][1].x, a[mt][2].x, a[mt][3].x,
                             b[nt][0].x, b[nt][1].x);
                    mma16816(acc[mt][nt],
                             a[mt][0].x, a[mt][1].x, a[mt][2].x, a[mt][3].x,
                             b[nt][0].y, b[nt][1].y);
                    mma16816(acc[mt][nt],
                             a[mt][0].y, a[mt][1].y, a[mt][2].y, a[mt][3].y,
                             b[nt][0].x, b[nt][1].x);
                }
            }
        }

        // online logsumexp over this 32-column slab
        #pragma unroll
        for (int mt = 0; mt < 4; mt++) {
            #pragma unroll
            for (int h = 0; h < 2; h++) {
                const int j = mt * 2 + h;
                float v[8];
                #pragma unroll
                for (int nt = 0; nt < 4; nt++) {
                    float2 bb = bps2[it * 128 + wid * 16 + nt * 4 + tig];
                    v[nt * 2]     = acc[mt][nt][2 * h]     + bb.x;
                    v[nt * 2 + 1] = acc[mt][nt][2 * h + 1] + bb.y;
                }
                float vmax = v[0];
                #pragma unroll
                for (int q = 1; q < 8; q++) vmax = fmaxf(vmax, v[q]);
                float mn = fmaxf(m[j], vmax);
                float as = 0.f;
                #pragma unroll
                for (int q = 0; q < 8; q++) as += __expf(v[q] - mn);
                s[j] = s[j] * __expf(m[j] - mn) + as;
                m[j] = mn;
            }
        }
    }

    // cross-tig merge (lanes sharing a row differ only in tig bits)
    #pragma unroll
    for (int j = 0; j < 8; j++) {
        #pragma unroll
        for (int off = 1; off <= 2; off <<= 1) {
            float m2 = __shfl_xor_sync(FULL, m[j], off);
            float s2 = __shfl_xor_sync(FULL, s[j], off);
            float mn = fmaxf(m[j], m2);
            s[j] = s[j] * __expf(m[j] - mn) + s2 * __expf(m2 - mn);
            m[j] = mn;
        }
        if (tig == 0) {
            red_m[(gid + 8 * j) * 8 + wid] = m[j];
            red_s[(gid + 8 * j) * 8 + wid] = s[j];
        }
    }
    __syncthreads();

    // cross-warp merge + write lse
    if (tid < 64) {
        float mm = -1e30f, ss = 0.f;
        #pragma unroll
        for (int w = 0; w < 8; w++) {
            float mw = red_m[tid * 8 + w], sw = red_s[tid * 8 + w];
            float mn = fmaxf(mm, mw);
            ss = ss * __expf(mm - mn) + sw * __expf(mw - mn);
            mm = mn;
        }
        g_lse[row0 + tid] = mm + __logf(ss);
    }
}

// ===========================================================================
// Kernel 6: gather 64 move logits (fp32 WpT dots), softmax-64, tanh evals.
// (byte-identical to the R6 passing build)
// ===========================================================================
__global__ __launch_bounds__(256, 2) void gather_kernel(
    const float* __restrict__ bp,
    const float* __restrict__ We, const float* __restrict__ be,
    const int* __restrict__ from_sq, const int* __restrict__ to_sq,
    float* __restrict__ out)
{
    __shared__ float hs[32 * HID];
    __shared__ float WhS[HID];
    __shared__ float WencS[128];

    float* out_probs = out;
    float* out_evals = out + (size_t)BATCH * NMOVES;

    const int tid = threadIdx.x;
    const int row0 = blockIdx.x * 32;
    const unsigned FULL = 0xffffffffu;

    {
        const float4* src = (const float4*)(g_h + (size_t)row0 * HID);
        float4* dst = (float4*)hs;
        for (int i = tid; i < 32 * HID / 4; i += 256) dst[i] = src[i];
    }
    WhS[tid] = We[tid];
    if (tid < 128) WencS[tid] = We[HID + tid];
    __syncthreads();

    const int lane = tid & 31;
    const int w = tid >> 5;
    const float be0 = be[0];

    for (int rr = 0; rr < 4; rr++) {
        const int lrow = w * 4 + rr;
        const int grow = row0 + lrow;
        const float* hrow = hs + lrow * HID;
        const float lse = g_lse[grow];

        float p = 0.f;
        #pragma unroll
        for (int j = 0; j < 8; j++) p = fmaf(hrow[lane * 8 + j], WhS[lane * 8 + j], p);
        #pragma unroll
        for (int off = 16; off; off >>= 1) p += __shfl_xor_sync(FULL, p, off);
        const float hwh = p;

        float lg[2];
        #pragma unroll
        for (int t = 0; t < 2; t++) {
            const int mI = lane + 32 * t;
            const int f  = from_sq[(size_t)grow * NMOVES + mI];
            const int tt = to_sq  [(size_t)grow * NMOVES + mI];
            const int idx = f * 64 + tt;
            const float4* wc  = (const float4*)(g_WpT + (size_t)idx * HID);
            const float4* hv4 = (const float4*)hrow;
            float acc = 0.f;
            #pragma unroll 4
            for (int k4 = 0; k4 < HID / 4; k4++) {
                float4 wv = wc[k4];
                float4 hv = hv4[k4];
                acc = fmaf(wv.x, hv.x, fmaf(wv.y, hv.y, fmaf(wv.z, hv.z, fmaf(wv.w, hv.w, acc))));
            }
            float lgt = acc + bp[idx] - lse;
            lg[t] = fminf(fmaxf(lgt, -10.f), 10.f);

            out_evals[(size_t)grow * NMOVES + mI] =
                tanhf(hwh + WencS[f] + WencS[64 + tt] + be0);
        }

        float mx = fmaxf(lg[0], lg[1]);
        #pragma unroll
        for (int off = 16; off; off >>= 1) mx = fmaxf(mx, __shfl_xor_sync(FULL, mx, off));
        float e0 = __expf(lg[0] - mx), e1 = __expf(lg[1] - mx);
        float ssum = e0 + e1;
        #pragma unroll
        for (int off = 16; off; off >>= 1) ssum += __shfl_xor_sync(FULL, ssum, off);
        float inv = 1.0f / ssum;
        out_probs[(size_t)grow * NMOVES + lane]      = e0 * inv;
        out_probs[(size_t)grow * NMOVES + lane + 32] = e1 * inv;
    }
}

// ===========================================================================
// kernel_launch — graph-capturable. Launch order puts policy_lse_kernel as
// the 6th launch so the harness's ncu (-s 5 -c 1) profiles it.
// ===========================================================================
extern "C" void kernel_launch(void* const* d_in, const int* in_sizes, int n_in,
                              void* d_out, int out_size)
{
    const float* pf   = (const float*)d_in[0];
    const float* mb   = (const float*)d_in[1];
    const float* ks   = (const float*)d_in[2];
    const float* mob  = (const float*)d_in[3];
    const float* ps   = (const float*)d_in[4];
    const int*   fsq  = (const int*)  d_in[5];
    const int*   tsq  = (const int*)  d_in[6];
    const float* W1   = (const float*)d_in[7];
    const float* b1   = (const float*)d_in[8];
    const float* W2   = (const float*)d_in[9];
    const float* b2   = (const float*)d_in[10];
    const float* W3   = (const float*)d_in[11];
    const float* b3   = (const float*)d_in[12];
    const float* We   = (const float*)d_in[13];
    const float* be   = (const float*)d_in[14];
    const float* Wp   = (const float*)d_in[15];
    const float* bp   = (const float*)d_in[16];
    float* out = (float*)d_out;

    cudaFuncSetAttribute(policy_lse_kernel,
                         cudaFuncAttributeMaxDynamicSharedMemorySize,
                         POL_SMEM);

    transpose_pack_kernel<<<dim3(NPOL / 32, HID / 32), dim3(32, 8)>>>(Wp);  // 1
    concat_kernel<<<(BATCH * LDK + 255) / 256, 256>>>(pf, mb, ks, mob, ps); // 2
    layer1_kernel<<<BATCH / 32, 256>>>(W1, b1);                             // 3
    layer2_kernel<<<BATCH / 32, 256>>>(W2, b2);                             // 4
    layer3_kernel<<<BATCH / 32, 256>>>(W3, b3);                             // 5
    policy_lse_kernel<<<BATCH / 64, 256, POL_SMEM>>>(bp);                   // 6 <- ncu
    gather_kernel<<<BATCH / 32, 256>>>(bp, We, be, fsq, tsq, out);          // 7
}